// round 16
// baseline (speedup 1.0000x reference)
#include <cuda_runtime.h>
#include <cuda_bf16.h>
#include <cuda_fp16.h>
#include <stdint.h>

#define NMAX   100000
#define F      128
#define DCAP   64          // bucket capacity per node (P(deg>64) ~ 0 for lambda=6.4)
#define OVFMAX 8192        // overflow-edge safety list

#define BM     128         // CTA tile rows
#define SMEM_BYTES_G1 (2 * BM * 136 * 2)   // gemm1: Ah + Al bf16 tiles
#define SMEM_BYTES_G2 (BM * 136 * 2)       // gemm2: single fp16 tile

// Scratch (allocation-free rule: __device__ globals)
__device__ __half g_xw_h [NMAX * F];      // layer-1 product, fp16 (gather source)
__device__ __half g_acc1h[NMAX * F];      // relu(layer-1 activation), fp16
__device__ __half g_hw_h [NMAX * F];      // layer-2 product, fp16 (gather source)
__device__ int    g_cursor[NMAX + 1];     // [N] = overflow counter
__device__ float  g_dinvf[NMAX];          // rsqrt(deg) table
__device__ int    g_eidx[NMAX * DCAP];    // per-dst neighbor buckets
__device__ int    g_ovf [2 * OVFMAX];     // (r,c) pairs that overflowed
// W1 in bf16 hi/lo mma B-fragment layout: [hl][ktile(8)][warp_n(4)][lane(32)][8 u32]
__device__ uint32_t g_wfrag_b[2][8][4][32][8];
// W2 in fp16 2-term fragment layout: [term][ktile(8)][warp_n(4)][lane(32)][8 u32]
__device__ uint32_t g_wfrag_h[2][8][4][32][8];

// ---------------------------------------------------------------------------
// Helpers
// ---------------------------------------------------------------------------
__device__ __forceinline__ uint32_t smem_u32(const void* p) {
    uint32_t a;
    asm("{ .reg .u64 t; cvta.to.shared.u64 t, %1; cvt.u32.u64 %0, t; }" : "=r"(a) : "l"(p));
    return a;
}
__device__ __forceinline__ uint32_t pack_hi(float a, float b) {
    __nv_bfloat16 x = __float2bfloat16_rn(a), y = __float2bfloat16_rn(b);
    return (uint32_t)*(unsigned short*)&x | ((uint32_t)*(unsigned short*)&y << 16);
}
__device__ __forceinline__ uint32_t pack_lo(float a, float b) {
    __nv_bfloat16 x = __float2bfloat16_rn(a), y = __float2bfloat16_rn(b);
    float ra = a - __bfloat162float(x), rb = b - __bfloat162float(y);
    __nv_bfloat16 lx = __float2bfloat16_rn(ra), ly = __float2bfloat16_rn(rb);
    return (uint32_t)*(unsigned short*)&lx | ((uint32_t)*(unsigned short*)&ly << 16);
}
__device__ __forceinline__ uint32_t pack_f16(float a, float b) {
    __half2 h = __float22half2_rn(make_float2(a, b));
    return *(uint32_t*)&h;
}
__device__ __forceinline__ void mma_bf16(float* d, const uint32_t* a, uint32_t b0, uint32_t b1) {
    asm volatile(
        "mma.sync.aligned.m16n8k16.row.col.f32.bf16.bf16.f32 "
        "{%0,%1,%2,%3}, {%4,%5,%6,%7}, {%8,%9}, {%0,%1,%2,%3};"
        : "+f"(d[0]), "+f"(d[1]), "+f"(d[2]), "+f"(d[3])
        : "r"(a[0]), "r"(a[1]), "r"(a[2]), "r"(a[3]), "r"(b0), "r"(b1));
}
__device__ __forceinline__ void mma_f16(float* d, const uint32_t* a, uint32_t b0, uint32_t b1) {
    asm volatile(
        "mma.sync.aligned.m16n8k16.row.col.f32.f16.f16.f32 "
        "{%0,%1,%2,%3}, {%4,%5,%6,%7}, {%8,%9}, {%0,%1,%2,%3};"
        : "+f"(d[0]), "+f"(d[1]), "+f"(d[2]), "+f"(d[3])
        : "r"(a[0]), "r"(a[1]), "r"(a[2]), "r"(a[3]), "r"(b0), "r"(b1));
}
__device__ __forceinline__ void ldsm4(uint32_t* r, uint32_t addr) {
    asm volatile("ldmatrix.sync.aligned.m8n8.x4.shared.b16 {%0,%1,%2,%3}, [%4];"
                 : "=r"(r[0]), "=r"(r[1]), "=r"(r[2]), "=r"(r[3]) : "r"(addr));
}
__device__ __forceinline__ void cp_async16(uint32_t dst, const void* src) {
    asm volatile("cp.async.ca.shared.global [%0], [%1], 16;"
                 :: "r"(dst), "l"(src) : "memory");
}

// ---------------------------------------------------------------------------
// W split: W1 -> bf16 hi/lo fragments; W2 -> fp16 hi + fp16 residual fragments.
// ---------------------------------------------------------------------------
__global__ void k_wsplit(const float* __restrict__ W1, const float* __restrict__ W2) {
    int id = blockIdx.x * blockDim.x + threadIdx.x;   // 32768 total
    if (id >= 2 * 16384) return;
    int which = id >> 14;          // 0 = W1/bf16, 1 = W2/fp16
    int v     = id & 16383;
    int jr   = v & 7;
    int lane = (v >> 3) & 31;
    int wn   = (v >> 8) & 3;
    int kt   = (v >> 10) & 7;
    int hl   = v >> 13;
    int j = jr >> 1, r = jr & 1;
    int n = (wn * 4 + j) * 8 + (lane >> 2);
    int k = kt * 16 + (lane & 3) * 2 + r * 8;
    if (which == 0) {
        float v0 = W1[k * F + n], v1 = W1[(k + 1) * F + n];
        g_wfrag_b[hl][kt][wn][lane][jr] = (hl == 0) ? pack_hi(v0, v1) : pack_lo(v0, v1);
    } else {
        float v0 = W2[k * F + n], v1 = W2[(k + 1) * F + n];
        if (hl == 0) {
            g_wfrag_h[0][kt][wn][lane][jr] = pack_f16(v0, v1);
        } else {
            float r0 = v0 - __half2float(__float2half_rn(v0));
            float r1 = v1 - __half2float(__float2half_rn(v1));
            g_wfrag_h[1][kt][wn][lane][jr] = pack_f16(r0, r1);
        }
    }
}

// dinv table (after scatter fills g_cursor)
__global__ void k_dinv(int N) {
    int i = blockIdx.x * blockDim.x + threadIdx.x;
    if (i < N) g_dinvf[i] = rsqrtf((float)(g_cursor[i] + 1));
}

// ---------------------------------------------------------------------------
// GEMM1 block body (bf16x3, fp32 A): 128-row CTA tile, warp tile 64x32.
// ---------------------------------------------------------------------------
__device__ __forceinline__ void gemm1_block(
    const float* __restrict__ A, __half* __restrict__ outH,
    int M, int bb, __nv_bfloat16* smem)
{
    __nv_bfloat16 (*Ah)[136] = (__nv_bfloat16(*)[136])smem;
    __nv_bfloat16 (*Al)[136] = (__nv_bfloat16(*)[136])(smem + BM * 136);

    const int tid  = threadIdx.x;
    const int wid  = tid >> 5;
    const int lane = tid & 31;
    const int wm = wid >> 2;
    const int wn = wid & 3;
    const int block_row = bb * BM;

    #pragma unroll
    for (int it = 0; it < 8; it++) {
        int seg = it * 256 + tid;
        int r  = seg >> 4;
        int sk = (seg & 15) * 8;
        int grow = block_row + r;
        float4 a0 = make_float4(0.f,0.f,0.f,0.f), a1 = a0;
        if (grow < M) {
            a0 = *(const float4*)(A + (size_t)grow * F + sk);
            a1 = *(const float4*)(A + (size_t)grow * F + sk + 4);
        }
        *(uint4*)&Ah[r][sk] = make_uint4(pack_hi(a0.x,a0.y), pack_hi(a0.z,a0.w),
                                         pack_hi(a1.x,a1.y), pack_hi(a1.z,a1.w));
        *(uint4*)&Al[r][sk] = make_uint4(pack_lo(a0.x,a0.y), pack_lo(a0.z,a0.w),
                                         pack_lo(a1.x,a1.y), pack_lo(a1.z,a1.w));
    }
    __syncthreads();

    float acc[4][4][4];
    #pragma unroll
    for (int mt = 0; mt < 4; mt++)
        #pragma unroll
        for (int j = 0; j < 4; j++)
            #pragma unroll
            for (int q = 0; q < 4; q++) acc[mt][j][q] = 0.f;

    const int mat = lane >> 3, rr = lane & 7;
    const int lrow  = (mat & 1) * 8 + rr;
    const int lkoff = (mat >> 1) * 8;
    const uint32_t aBaseH = smem_u32(&Ah[0][0]);
    const uint32_t aBaseL = smem_u32(&Al[0][0]);

    #pragma unroll
    for (int ks = 0; ks < 8; ks++) {
        const uint32_t* p_h = &g_wfrag_b[0][ks][wn][lane][0];
        const uint32_t* p_l = &g_wfrag_b[1][ks][wn][lane][0];
        uint4 h0 = *(const uint4*)p_h, h1 = *(const uint4*)(p_h + 4);
        uint4 l0 = *(const uint4*)p_l, l1 = *(const uint4*)(p_l + 4);
        uint32_t bh[8] = {h0.x,h0.y,h0.z,h0.w,h1.x,h1.y,h1.z,h1.w};
        uint32_t bl[8] = {l0.x,l0.y,l0.z,l0.w,l1.x,l1.y,l1.z,l1.w};

        #pragma unroll
        for (int mt = 0; mt < 4; mt++) {
            uint32_t ah[4], al[4];
            uint32_t off = (uint32_t)(((wm * 64 + mt * 16 + lrow) * 136 + ks * 16 + lkoff) * 2);
            ldsm4(ah, aBaseH + off);
            ldsm4(al, aBaseL + off);
            #pragma unroll
            for (int j = 0; j < 4; j++) {
                mma_bf16(acc[mt][j], ah, bh[2*j], bh[2*j+1]);
                mma_bf16(acc[mt][j], ah, bl[2*j], bl[2*j+1]);
                mma_bf16(acc[mt][j], al, bh[2*j], bh[2*j+1]);
            }
        }
    }

    const int qrow = lane >> 2;
    const int qcol = (lane & 3) * 2;
    #pragma unroll
    for (int mt = 0; mt < 4; mt++) {
        int r0 = block_row + wm * 64 + mt * 16 + qrow;
        int r1 = r0 + 8;
        #pragma unroll
        for (int j = 0; j < 4; j++) {
            int c = wn * 32 + j * 8 + qcol;
            if (r0 < M)
                *(__half2*)(outH + (size_t)r0 * F + c) =
                    __float22half2_rn(make_float2(acc[mt][j][0], acc[mt][j][1]));
            if (r1 < M)
                *(__half2*)(outH + (size_t)r1 * F + c) =
                    __float22half2_rn(make_float2(acc[mt][j][2], acc[mt][j][3]));
        }
    }
}

// ---------------------------------------------------------------------------
// Mega kernel 1: GEMM1 blocks + edge-scatter blocks (independent work)
// ---------------------------------------------------------------------------
__global__ void __launch_bounds__(256, 2)
k_mega1(const float* __restrict__ A, __half* __restrict__ outH,
        const int* __restrict__ ei, int M, int E, int gemm_blocks)
{
    extern __shared__ __nv_bfloat16 smem_dyn[];
    if ((int)blockIdx.x < gemm_blocks) {
        gemm1_block(A, outH, M, blockIdx.x, smem_dyn);
        return;
    }
    int e = (blockIdx.x - gemm_blocks) * 256 + threadIdx.x;
    if (e < E) {
        int r = __ldg(ei + e);
        int c = __ldg(ei + E + e);
        int pos = atomicAdd(&g_cursor[c], 1);
        if (pos < DCAP) {
            g_eidx[(size_t)c * DCAP + pos] = r;
        } else {
            int o = atomicAdd(&g_cursor[NMAX], 1);
            if (o < OVFMAX) { g_ovf[2 * o] = r; g_ovf[2 * o + 1] = c; }
        }
    }
}

// ---------------------------------------------------------------------------
// GEMM2: A fp16 (already ReLU'd), cp.async fill, fp16 2-term W, fp16 out.
// ---------------------------------------------------------------------------
__global__ void __launch_bounds__(256, 2)
k_gemm2(const __half* __restrict__ A, __half* __restrict__ outH, int M)
{
    extern __shared__ __half smem_h[];
    __half (*As)[136] = (__half(*)[136])smem_h;

    const int tid  = threadIdx.x;
    const int wid  = tid >> 5;
    const int lane = tid & 31;
    const int wm = wid >> 2;
    const int wn = wid & 3;
    const int block_row = blockIdx.x * BM;

    // Fill: 128 rows x 16 chunks(16B = 8 halves) = 2048 cp.async / 256 thr = 8 each
    #pragma unroll
    for (int it = 0; it < 8; it++) {
        int seg = it * 256 + tid;
        int r  = seg >> 4;
        int ch = (seg & 15) * 8;
        int grow = block_row + r;
        uint32_t dst = smem_u32(&As[r][ch]);
        if (grow < M) {
            cp_async16(dst, A + (size_t)grow * F + ch);
        } else {
            *(uint4*)&As[r][ch] = make_uint4(0u, 0u, 0u, 0u);
        }
    }
    asm volatile("cp.async.commit_group;" ::: "memory");
    asm volatile("cp.async.wait_group 0;" ::: "memory");
    __syncthreads();

    float acc[4][4][4];
    #pragma unroll
    for (int mt = 0; mt < 4; mt++)
        #pragma unroll
        for (int j = 0; j < 4; j++)
            #pragma unroll
            for (int q = 0; q < 4; q++) acc[mt][j][q] = 0.f;

    const int mat = lane >> 3, rr = lane & 7;
    const int lrow  = (mat & 1) * 8 + rr;
    const int lkoff = (mat >> 1) * 8;
    const uint32_t aBase = smem_u32(&As[0][0]);

    #pragma unroll
    for (int ks = 0; ks < 8; ks++) {
        const uint32_t* p_h = &g_wfrag_h[0][ks][wn][lane][0];
        const uint32_t* p_l = &g_wfrag_h[1][ks][wn][lane][0];
        uint4 h0 = *(const uint4*)p_h, h1 = *(const uint4*)(p_h + 4);
        uint4 l0 = *(const uint4*)p_l, l1 = *(const uint4*)(p_l + 4);
        uint32_t bh[8] = {h0.x,h0.y,h0.z,h0.w,h1.x,h1.y,h1.z,h1.w};
        uint32_t bl[8] = {l0.x,l0.y,l0.z,l0.w,l1.x,l1.y,l1.z,l1.w};

        #pragma unroll
        for (int mt = 0; mt < 4; mt++) {
            uint32_t af[4];
            uint32_t off = (uint32_t)(((wm * 64 + mt * 16 + lrow) * 136 + ks * 16 + lkoff) * 2);
            ldsm4(af, aBase + off);
            #pragma unroll
            for (int j = 0; j < 4; j++) {
                mma_f16(acc[mt][j], af, bh[2*j], bh[2*j+1]);
                mma_f16(acc[mt][j], af, bl[2*j], bl[2*j+1]);
            }
        }
    }

    const int qrow = lane >> 2;
    const int qcol = (lane & 3) * 2;
    #pragma unroll
    for (int mt = 0; mt < 4; mt++) {
        int r0 = block_row + wm * 64 + mt * 16 + qrow;
        int r1 = r0 + 8;
        #pragma unroll
        for (int j = 0; j < 4; j++) {
            int c = wn * 32 + j * 8 + qcol;
            if (r0 < M)
                *(__half2*)(outH + (size_t)r0 * F + c) =
                    __float22half2_rn(make_float2(acc[mt][j][0], acc[mt][j][1]));
            if (r1 < M)
                *(__half2*)(outH + (size_t)r1 * F + c) =
                    __float22half2_rn(make_float2(acc[mt][j][2], acc[mt][j][3]));
        }
    }
}

// ---------------------------------------------------------------------------
// Bucket-gather aggregation: one warp per destination node, fp16 source.
// Batch phase: lanes load ids AND weights in parallel.
// Inner loop: 4-wide pipelined — 8 shfls, 4 independent LDGs, then math.
// ---------------------------------------------------------------------------
__device__ __forceinline__ void acc_half4(float4& acc, uint2 u, float w) {
    float2 lo = __half22float2(*(const __half2*)&u.x);
    float2 hi = __half22float2(*(const __half2*)&u.y);
    acc.x = fmaf(lo.x, w, acc.x);
    acc.y = fmaf(lo.y, w, acc.y);
    acc.z = fmaf(hi.x, w, acc.z);
    acc.w = fmaf(hi.y, w, acc.w);
}

template <bool HOUT>
__global__ void __launch_bounds__(256)
k_agg(const __half* __restrict__ src, const float* __restrict__ bias,
      void* __restrict__ dst, int N)
{
    int node = blockIdx.x * (blockDim.x >> 5) + (threadIdx.x >> 5);
    if (node >= N) return;
    int lane = threadIdx.x & 31;

    int cr = __ldg(&g_cursor[node]);
    float dc = __ldg(&g_dinvf[node]);
    float s  = dc * dc;

    float4 acc = __ldg((const float4*)bias + lane);
    acc_half4(acc, __ldg((const uint2*)(src + (size_t)node * F) + lane), s);

    int cnt = min(cr, DCAP);
    const int* bucket = g_eidx + (size_t)node * DCAP;

    for (int base = 0; base < cnt; base += 32) {
        int id = 0; float wt = 0.f;
        if (base + lane < cnt) {
            id = __ldg(bucket + base + lane);
            wt = dc * __ldg(&g_dinvf[id]);       // computed lane-parallel
        }
        int m = min(cnt - base, 32);
        int j = 0;
        for (; j + 4 <= m; j += 4) {
            int   r0 = __shfl_sync(0xffffffff, id, j);
            int   r1 = __shfl_sync(0xffffffff, id, j + 1);
            int   r2 = __shfl_sync(0xffffffff, id, j + 2);
            int   r3 = __shfl_sync(0xffffffff, id, j + 3);
            float w0 = __shfl_sync(0xffffffff, wt, j);
            float w1 = __shfl_sync(0xffffffff, wt, j + 1);
            float w2 = __shfl_sync(0xffffffff, wt, j + 2);
            float w3 = __shfl_sync(0xffffffff, wt, j + 3);
            uint2 u0 = __ldg((const uint2*)(src + (size_t)r0 * F) + lane);
            uint2 u1 = __ldg((const uint2*)(src + (size_t)r1 * F) + lane);
            uint2 u2 = __ldg((const uint2*)(src + (size_t)r2 * F) + lane);
            uint2 u3 = __ldg((const uint2*)(src + (size_t)r3 * F) + lane);
            acc_half4(acc, u0, w0);
            acc_half4(acc, u1, w1);
            acc_half4(acc, u2, w2);
            acc_half4(acc, u3, w3);
        }
        for (; j < m; j++) {
            int   r = __shfl_sync(0xffffffff, id, j);
            float w = __shfl_sync(0xffffffff, wt, j);
            acc_half4(acc, __ldg((const uint2*)(src + (size_t)r * F) + lane), w);
        }
    }

    // Overflow slow path (empty in practice; correctness insurance)
    if (cr > DCAP) {
        int ovfn = min(__ldg(&g_cursor[NMAX]), OVFMAX);
        for (int e = 0; e < ovfn; e++) {
            if (g_ovf[2 * e + 1] == node) {
                int r = g_ovf[2 * e];
                float w = dc * __ldg(&g_dinvf[r]);
                acc_half4(acc, __ldg((const uint2*)(src + (size_t)r * F) + lane), w);
            }
        }
    }

    if constexpr (HOUT) {
        acc.x = fmaxf(acc.x, 0.f); acc.y = fmaxf(acc.y, 0.f);
        acc.z = fmaxf(acc.z, 0.f); acc.w = fmaxf(acc.w, 0.f);
        __half2 h0 = __float22half2_rn(make_float2(acc.x, acc.y));
        __half2 h1 = __float22half2_rn(make_float2(acc.z, acc.w));
        uint2 u = make_uint2(*(uint32_t*)&h0, *(uint32_t*)&h1);
        *((uint2*)((__half*)dst + (size_t)node * F) + lane) = u;
    } else {
        *((float4*)((float*)dst + (size_t)node * F) + lane) = acc;
    }
}

// ---------------------------------------------------------------------------
// Launch
// ---------------------------------------------------------------------------
extern "C" void kernel_launch(void* const* d_in, const int* in_sizes, int n_in,
                              void* d_out, int out_size)
{
    const float* x  = (const float*)d_in[0];
    const int*   ei = (const int*)d_in[1];
    const float* W1 = (const float*)d_in[2];
    const float* b1 = (const float*)d_in[3];
    const float* W2 = (const float*)d_in[4];
    const float* b2 = (const float*)d_in[5];
    float*       out = (float*)d_out;

    const int N = in_sizes[0] / F;   // 100000
    const int E = in_sizes[1] / 2;   // 640000

    __half* xwh;   cudaGetSymbolAddress((void**)&xwh,   g_xw_h);
    __half* acc1h; cudaGetSymbolAddress((void**)&acc1h, g_acc1h);
    __half* hwh;   cudaGetSymbolAddress((void**)&hwh,   g_hw_h);
    int* cursor;   cudaGetSymbolAddress((void**)&cursor, g_cursor);

    cudaFuncSetAttribute(k_mega1, cudaFuncAttributeMaxDynamicSharedMemorySize, SMEM_BYTES_G1);
    cudaFuncSetAttribute(k_gemm2, cudaFuncAttributeMaxDynamicSharedMemorySize, SMEM_BYTES_G2);

    const int gemm_blocks = (N + BM - 1) / BM;
    const int scat_blocks = (E + 255) / 256;
    const int agg_blocks  = (N + 7) / 8;

    // Zero bucket cursors + overflow counter
    cudaMemsetAsync(cursor, 0, (NMAX + 1) * sizeof(int));

    // W pre-split (both layers, one launch)
    k_wsplit<<<128, 256>>>(W1, W2);

    // GEMM1 + edge scatter fused: xw_h = (x @ W1) as fp16
    k_mega1<<<gemm_blocks + scat_blocks, 256, SMEM_BYTES_G1>>>(x, xwh, ei, N, E, gemm_blocks);

    // dinv table (needs final cursor counts)
    k_dinv<<<(N + 255) / 256, 256>>>(N);

    // Layer 1 aggregation: acc1h = relu(Â·xw_h + b1) as fp16
    k_agg<true><<<agg_blocks, 256>>>(xwh, b1, acc1h, N);

    // Layer 2 GEMM: hw_h = (acc1h @ W2) as fp16  (cp.async fill, 2-term fp16)
    k_gemm2<<<gemm_blocks, 256, SMEM_BYTES_G2>>>(acc1h, hwh, N);

    // Final aggregation: out = Â·hw_h + b2  (fp32)
    k_agg<false><<<agg_blocks, 256>>>(hwh, b2, out, N);
}

// round 17
// speedup vs baseline: 1.0640x; 1.0640x over previous
#include <cuda_runtime.h>
#include <cuda_bf16.h>
#include <cuda_fp16.h>
#include <stdint.h>

#define NMAX   100000
#define F      128
#define DCAP   64          // bucket capacity per node (P(deg>64) ~ 0 for lambda=6.4)
#define OVFMAX 8192        // overflow-edge safety list

#define BM     128         // CTA tile rows
#define SMEM_BYTES_G1 (2 * BM * 136 * 2)   // gemm1: Ah + Al bf16 tiles
#define SMEM_BYTES_G2 (BM * 136 * 2)       // gemm2: single fp16 tile

// Scratch (allocation-free rule: __device__ globals)
__device__ __half g_xw_h [NMAX * F];      // layer-1 product, fp16 (gather source)
__device__ __half g_acc1h[NMAX * F];      // relu(layer-1 activation), fp16
__device__ __half g_hw_h [NMAX * F];      // layer-2 product, fp16 (gather source)
__device__ int    g_cursor[NMAX + 1];     // [N] = overflow counter
__device__ float  g_dinvf[NMAX];          // rsqrt(deg) table
__device__ int    g_eidx[NMAX * DCAP];    // per-dst neighbor buckets
__device__ int    g_ovf [2 * OVFMAX];     // (r,c) pairs that overflowed
// W1 in bf16 hi/lo mma B-fragment layout: [hl][ktile(8)][warp_n(4)][lane(32)][8 u32]
__device__ uint32_t g_wfrag_b[2][8][4][32][8];
// W2 in fp16 2-term fragment layout: [term][ktile(8)][warp_n(4)][lane(32)][8 u32]
__device__ uint32_t g_wfrag_h[2][8][4][32][8];

// ---------------------------------------------------------------------------
// Helpers
// ---------------------------------------------------------------------------
__device__ __forceinline__ uint32_t smem_u32(const void* p) {
    uint32_t a;
    asm("{ .reg .u64 t; cvta.to.shared.u64 t, %1; cvt.u32.u64 %0, t; }" : "=r"(a) : "l"(p));
    return a;
}
__device__ __forceinline__ uint32_t pack_hi(float a, float b) {
    __nv_bfloat16 x = __float2bfloat16_rn(a), y = __float2bfloat16_rn(b);
    return (uint32_t)*(unsigned short*)&x | ((uint32_t)*(unsigned short*)&y << 16);
}
__device__ __forceinline__ uint32_t pack_lo(float a, float b) {
    __nv_bfloat16 x = __float2bfloat16_rn(a), y = __float2bfloat16_rn(b);
    float ra = a - __bfloat162float(x), rb = b - __bfloat162float(y);
    __nv_bfloat16 lx = __float2bfloat16_rn(ra), ly = __float2bfloat16_rn(rb);
    return (uint32_t)*(unsigned short*)&lx | ((uint32_t)*(unsigned short*)&ly << 16);
}
__device__ __forceinline__ uint32_t pack_f16(float a, float b) {
    __half2 h = __float22half2_rn(make_float2(a, b));
    return *(uint32_t*)&h;
}
__device__ __forceinline__ void mma_bf16(float* d, const uint32_t* a, uint32_t b0, uint32_t b1) {
    asm volatile(
        "mma.sync.aligned.m16n8k16.row.col.f32.bf16.bf16.f32 "
        "{%0,%1,%2,%3}, {%4,%5,%6,%7}, {%8,%9}, {%0,%1,%2,%3};"
        : "+f"(d[0]), "+f"(d[1]), "+f"(d[2]), "+f"(d[3])
        : "r"(a[0]), "r"(a[1]), "r"(a[2]), "r"(a[3]), "r"(b0), "r"(b1));
}
__device__ __forceinline__ void mma_f16(float* d, const uint32_t* a, uint32_t b0, uint32_t b1) {
    asm volatile(
        "mma.sync.aligned.m16n8k16.row.col.f32.f16.f16.f32 "
        "{%0,%1,%2,%3}, {%4,%5,%6,%7}, {%8,%9}, {%0,%1,%2,%3};"
        : "+f"(d[0]), "+f"(d[1]), "+f"(d[2]), "+f"(d[3])
        : "r"(a[0]), "r"(a[1]), "r"(a[2]), "r"(a[3]), "r"(b0), "r"(b1));
}
__device__ __forceinline__ void ldsm4(uint32_t* r, uint32_t addr) {
    asm volatile("ldmatrix.sync.aligned.m8n8.x4.shared.b16 {%0,%1,%2,%3}, [%4];"
                 : "=r"(r[0]), "=r"(r[1]), "=r"(r[2]), "=r"(r[3]) : "r"(addr));
}
__device__ __forceinline__ void cp_async16(uint32_t dst, const void* src) {
    asm volatile("cp.async.ca.shared.global [%0], [%1], 16;"
                 :: "r"(dst), "l"(src) : "memory");
}

// ---------------------------------------------------------------------------
// W split: W1 -> bf16 hi/lo fragments; W2 -> fp16 hi + fp16 residual fragments.
// ---------------------------------------------------------------------------
__global__ void k_wsplit(const float* __restrict__ W1, const float* __restrict__ W2) {
    int id = blockIdx.x * blockDim.x + threadIdx.x;   // 32768 total
    if (id >= 2 * 16384) return;
    int which = id >> 14;          // 0 = W1/bf16, 1 = W2/fp16
    int v     = id & 16383;
    int jr   = v & 7;
    int lane = (v >> 3) & 31;
    int wn   = (v >> 8) & 3;
    int kt   = (v >> 10) & 7;
    int hl   = v >> 13;
    int j = jr >> 1, r = jr & 1;
    int n = (wn * 4 + j) * 8 + (lane >> 2);
    int k = kt * 16 + (lane & 3) * 2 + r * 8;
    if (which == 0) {
        float v0 = W1[k * F + n], v1 = W1[(k + 1) * F + n];
        g_wfrag_b[hl][kt][wn][lane][jr] = (hl == 0) ? pack_hi(v0, v1) : pack_lo(v0, v1);
    } else {
        float v0 = W2[k * F + n], v1 = W2[(k + 1) * F + n];
        if (hl == 0) {
            g_wfrag_h[0][kt][wn][lane][jr] = pack_f16(v0, v1);
        } else {
            float r0 = v0 - __half2float(__float2half_rn(v0));
            float r1 = v1 - __half2float(__float2half_rn(v1));
            g_wfrag_h[1][kt][wn][lane][jr] = pack_f16(r0, r1);
        }
    }
}

// dinv table (after scatter fills g_cursor)
__global__ void k_dinv(int N) {
    int i = blockIdx.x * blockDim.x + threadIdx.x;
    if (i < N) g_dinvf[i] = rsqrtf((float)(g_cursor[i] + 1));
}

// ---------------------------------------------------------------------------
// GEMM1 block body (bf16x3, fp32 A): 128-row CTA tile, warp tile 64x32.
// ---------------------------------------------------------------------------
__device__ __forceinline__ void gemm1_block(
    const float* __restrict__ A, __half* __restrict__ outH,
    int M, int bb, __nv_bfloat16* smem)
{
    __nv_bfloat16 (*Ah)[136] = (__nv_bfloat16(*)[136])smem;
    __nv_bfloat16 (*Al)[136] = (__nv_bfloat16(*)[136])(smem + BM * 136);

    const int tid  = threadIdx.x;
    const int wid  = tid >> 5;
    const int lane = tid & 31;
    const int wm = wid >> 2;
    const int wn = wid & 3;
    const int block_row = bb * BM;

    #pragma unroll
    for (int it = 0; it < 8; it++) {
        int seg = it * 256 + tid;
        int r  = seg >> 4;
        int sk = (seg & 15) * 8;
        int grow = block_row + r;
        float4 a0 = make_float4(0.f,0.f,0.f,0.f), a1 = a0;
        if (grow < M) {
            a0 = *(const float4*)(A + (size_t)grow * F + sk);
            a1 = *(const float4*)(A + (size_t)grow * F + sk + 4);
        }
        *(uint4*)&Ah[r][sk] = make_uint4(pack_hi(a0.x,a0.y), pack_hi(a0.z,a0.w),
                                         pack_hi(a1.x,a1.y), pack_hi(a1.z,a1.w));
        *(uint4*)&Al[r][sk] = make_uint4(pack_lo(a0.x,a0.y), pack_lo(a0.z,a0.w),
                                         pack_lo(a1.x,a1.y), pack_lo(a1.z,a1.w));
    }
    __syncthreads();

    float acc[4][4][4];
    #pragma unroll
    for (int mt = 0; mt < 4; mt++)
        #pragma unroll
        for (int j = 0; j < 4; j++)
            #pragma unroll
            for (int q = 0; q < 4; q++) acc[mt][j][q] = 0.f;

    const int mat = lane >> 3, rr = lane & 7;
    const int lrow  = (mat & 1) * 8 + rr;
    const int lkoff = (mat >> 1) * 8;
    const uint32_t aBaseH = smem_u32(&Ah[0][0]);
    const uint32_t aBaseL = smem_u32(&Al[0][0]);

    #pragma unroll
    for (int ks = 0; ks < 8; ks++) {
        const uint32_t* p_h = &g_wfrag_b[0][ks][wn][lane][0];
        const uint32_t* p_l = &g_wfrag_b[1][ks][wn][lane][0];
        uint4 h0 = *(const uint4*)p_h, h1 = *(const uint4*)(p_h + 4);
        uint4 l0 = *(const uint4*)p_l, l1 = *(const uint4*)(p_l + 4);
        uint32_t bh[8] = {h0.x,h0.y,h0.z,h0.w,h1.x,h1.y,h1.z,h1.w};
        uint32_t bl[8] = {l0.x,l0.y,l0.z,l0.w,l1.x,l1.y,l1.z,l1.w};

        #pragma unroll
        for (int mt = 0; mt < 4; mt++) {
            uint32_t ah[4], al[4];
            uint32_t off = (uint32_t)(((wm * 64 + mt * 16 + lrow) * 136 + ks * 16 + lkoff) * 2);
            ldsm4(ah, aBaseH + off);
            ldsm4(al, aBaseL + off);
            #pragma unroll
            for (int j = 0; j < 4; j++) {
                mma_bf16(acc[mt][j], ah, bh[2*j], bh[2*j+1]);
                mma_bf16(acc[mt][j], ah, bl[2*j], bl[2*j+1]);
                mma_bf16(acc[mt][j], al, bh[2*j], bh[2*j+1]);
            }
        }
    }

    const int qrow = lane >> 2;
    const int qcol = (lane & 3) * 2;
    #pragma unroll
    for (int mt = 0; mt < 4; mt++) {
        int r0 = block_row + wm * 64 + mt * 16 + qrow;
        int r1 = r0 + 8;
        #pragma unroll
        for (int j = 0; j < 4; j++) {
            int c = wn * 32 + j * 8 + qcol;
            if (r0 < M)
                *(__half2*)(outH + (size_t)r0 * F + c) =
                    __float22half2_rn(make_float2(acc[mt][j][0], acc[mt][j][1]));
            if (r1 < M)
                *(__half2*)(outH + (size_t)r1 * F + c) =
                    __float22half2_rn(make_float2(acc[mt][j][2], acc[mt][j][3]));
        }
    }
}

// ---------------------------------------------------------------------------
// Mega kernel 1: GEMM1 blocks + edge-scatter blocks (independent work)
// ---------------------------------------------------------------------------
__global__ void __launch_bounds__(256, 2)
k_mega1(const float* __restrict__ A, __half* __restrict__ outH,
        const int* __restrict__ ei, int M, int E, int gemm_blocks)
{
    extern __shared__ __nv_bfloat16 smem_dyn[];
    if ((int)blockIdx.x < gemm_blocks) {
        gemm1_block(A, outH, M, blockIdx.x, smem_dyn);
        return;
    }
    int e = (blockIdx.x - gemm_blocks) * 256 + threadIdx.x;
    if (e < E) {
        int r = __ldg(ei + e);
        int c = __ldg(ei + E + e);
        int pos = atomicAdd(&g_cursor[c], 1);
        if (pos < DCAP) {
            g_eidx[(size_t)c * DCAP + pos] = r;
        } else {
            int o = atomicAdd(&g_cursor[NMAX], 1);
            if (o < OVFMAX) { g_ovf[2 * o] = r; g_ovf[2 * o + 1] = c; }
        }
    }
}

// ---------------------------------------------------------------------------
// GEMM2: A fp16 (already ReLU'd), cp.async fill, fp16 2-term W, fp16 out.
// ---------------------------------------------------------------------------
__global__ void __launch_bounds__(256, 2)
k_gemm2(const __half* __restrict__ A, __half* __restrict__ outH, int M)
{
    extern __shared__ __half smem_h[];
    __half (*As)[136] = (__half(*)[136])smem_h;

    const int tid  = threadIdx.x;
    const int wid  = tid >> 5;
    const int lane = tid & 31;
    const int wm = wid >> 2;
    const int wn = wid & 3;
    const int block_row = blockIdx.x * BM;

    #pragma unroll
    for (int it = 0; it < 8; it++) {
        int seg = it * 256 + tid;
        int r  = seg >> 4;
        int ch = (seg & 15) * 8;
        int grow = block_row + r;
        uint32_t dst = smem_u32(&As[r][ch]);
        if (grow < M) {
            cp_async16(dst, A + (size_t)grow * F + ch);
        } else {
            *(uint4*)&As[r][ch] = make_uint4(0u, 0u, 0u, 0u);
        }
    }
    asm volatile("cp.async.commit_group;" ::: "memory");
    asm volatile("cp.async.wait_group 0;" ::: "memory");
    __syncthreads();

    float acc[4][4][4];
    #pragma unroll
    for (int mt = 0; mt < 4; mt++)
        #pragma unroll
        for (int j = 0; j < 4; j++)
            #pragma unroll
            for (int q = 0; q < 4; q++) acc[mt][j][q] = 0.f;

    const int mat = lane >> 3, rr = lane & 7;
    const int lrow  = (mat & 1) * 8 + rr;
    const int lkoff = (mat >> 1) * 8;
    const uint32_t aBase = smem_u32(&As[0][0]);

    #pragma unroll
    for (int ks = 0; ks < 8; ks++) {
        const uint32_t* p_h = &g_wfrag_h[0][ks][wn][lane][0];
        const uint32_t* p_l = &g_wfrag_h[1][ks][wn][lane][0];
        uint4 h0 = *(const uint4*)p_h, h1 = *(const uint4*)(p_h + 4);
        uint4 l0 = *(const uint4*)p_l, l1 = *(const uint4*)(p_l + 4);
        uint32_t bh[8] = {h0.x,h0.y,h0.z,h0.w,h1.x,h1.y,h1.z,h1.w};
        uint32_t bl[8] = {l0.x,l0.y,l0.z,l0.w,l1.x,l1.y,l1.z,l1.w};

        #pragma unroll
        for (int mt = 0; mt < 4; mt++) {
            uint32_t af[4];
            uint32_t off = (uint32_t)(((wm * 64 + mt * 16 + lrow) * 136 + ks * 16 + lkoff) * 2);
            ldsm4(af, aBase + off);
            #pragma unroll
            for (int j = 0; j < 4; j++) {
                mma_f16(acc[mt][j], af, bh[2*j], bh[2*j+1]);
                mma_f16(acc[mt][j], af, bl[2*j], bl[2*j+1]);
            }
        }
    }

    const int qrow = lane >> 2;
    const int qcol = (lane & 3) * 2;
    #pragma unroll
    for (int mt = 0; mt < 4; mt++) {
        int r0 = block_row + wm * 64 + mt * 16 + qrow;
        int r1 = r0 + 8;
        #pragma unroll
        for (int j = 0; j < 4; j++) {
            int c = wn * 32 + j * 8 + qcol;
            if (r0 < M)
                *(__half2*)(outH + (size_t)r0 * F + c) =
                    __float22half2_rn(make_float2(acc[mt][j][0], acc[mt][j][1]));
            if (r1 < M)
                *(__half2*)(outH + (size_t)r1 * F + c) =
                    __float22half2_rn(make_float2(acc[mt][j][2], acc[mt][j][3]));
        }
    }
}

// ---------------------------------------------------------------------------
// Bucket-gather aggregation: TWO nodes per warp (one per 16-lane half).
// Each lane covers 16B (8 halves) of its node's row -> LDG.128 moves 512B/warp.
// Loop runs max(deg_a, deg_b) instead of deg_a + deg_b across two warps.
// ---------------------------------------------------------------------------
__device__ __forceinline__ void acc_half8(float4& a, float4& b, uint4 u, float w) {
    float2 f0 = __half22float2(*(const __half2*)&u.x);
    float2 f1 = __half22float2(*(const __half2*)&u.y);
    float2 f2 = __half22float2(*(const __half2*)&u.z);
    float2 f3 = __half22float2(*(const __half2*)&u.w);
    a.x = fmaf(f0.x, w, a.x); a.y = fmaf(f0.y, w, a.y);
    a.z = fmaf(f1.x, w, a.z); a.w = fmaf(f1.y, w, a.w);
    b.x = fmaf(f2.x, w, b.x); b.y = fmaf(f2.y, w, b.y);
    b.z = fmaf(f3.x, w, b.z); b.w = fmaf(f3.y, w, b.w);
}

template <bool HOUT>
__global__ void __launch_bounds__(256)
k_agg(const __half* __restrict__ src, const float* __restrict__ bias,
      void* __restrict__ dst, int N)
{
    int warp = blockIdx.x * (blockDim.x >> 5) + (threadIdx.x >> 5);
    int lane = threadIdx.x & 31;
    int sub  = lane >> 4;          // which node this half-warp owns
    int l16  = lane & 15;          // lane within half: covers cols l16*8..+7
    int node = warp * 2 + sub;
    bool valid = node < N;
    if (warp * 2 >= N) return;
    int nc = valid ? node : 0;     // safe address

    int   cr = valid ? __ldg(&g_cursor[nc]) : 0;
    float dc = valid ? __ldg(&g_dinvf[nc]) : 0.f;
    float s  = dc * dc;

    // accumulators: 8 columns per lane
    const float4* bp = (const float4*)bias + l16 * 2;
    float4 accA = __ldg(bp);
    float4 accB = __ldg(bp + 1);
    {
        uint4 u = __ldg((const uint4*)(src + (size_t)nc * F) + l16);
        acc_half8(accA, accB, u, s);    // s=0 when invalid
    }

    int cnt = min(cr, DCAP);
    const int* bucket = g_eidx + (size_t)nc * DCAP;
    int cmax = max(cnt, __shfl_xor_sync(0xffffffff, cnt, 16));

    for (int base = 0; base < cmax; base += 16) {
        int id = 0; float wt = 0.f;
        if (base + l16 < cnt) {
            id = __ldg(bucket + base + l16);
            wt = dc * __ldg(&g_dinvf[id]);     // lane-parallel weight compute
        }
        int m = cnt - base; m = m < 0 ? 0 : (m > 16 ? 16 : m);
        int mm = max(m, __shfl_xor_sync(0xffffffff, m, 16));
        #pragma unroll 4
        for (int j = 0; j < mm; j++) {
            int   r = __shfl_sync(0xffffffff, id, (sub << 4) + j);
            float w = __shfl_sync(0xffffffff, wt, (sub << 4) + j);
            if (j < m) {
                uint4 u = __ldg((const uint4*)(src + (size_t)r * F) + l16);
                acc_half8(accA, accB, u, w);
            }
        }
    }

    // Overflow slow path (empty in practice; correctness insurance)
    if (cr > DCAP) {
        int ovfn = min(__ldg(&g_cursor[NMAX]), OVFMAX);
        for (int e = 0; e < ovfn; e++) {
            if (g_ovf[2 * e + 1] == node) {
                int r = g_ovf[2 * e];
                float w = dc * __ldg(&g_dinvf[r]);
                uint4 u = __ldg((const uint4*)(src + (size_t)r * F) + l16);
                acc_half8(accA, accB, u, w);
            }
        }
    }

    if (!valid) return;
    if constexpr (HOUT) {
        accA.x = fmaxf(accA.x, 0.f); accA.y = fmaxf(accA.y, 0.f);
        accA.z = fmaxf(accA.z, 0.f); accA.w = fmaxf(accA.w, 0.f);
        accB.x = fmaxf(accB.x, 0.f); accB.y = fmaxf(accB.y, 0.f);
        accB.z = fmaxf(accB.z, 0.f); accB.w = fmaxf(accB.w, 0.f);
        __half2 h0 = __float22half2_rn(make_float2(accA.x, accA.y));
        __half2 h1 = __float22half2_rn(make_float2(accA.z, accA.w));
        __half2 h2 = __float22half2_rn(make_float2(accB.x, accB.y));
        __half2 h3 = __float22half2_rn(make_float2(accB.z, accB.w));
        uint4 u = make_uint4(*(uint32_t*)&h0, *(uint32_t*)&h1,
                             *(uint32_t*)&h2, *(uint32_t*)&h3);
        *((uint4*)((__half*)dst + (size_t)node * F) + l16) = u;
    } else {
        float4* dp = (float4*)((float*)dst + (size_t)node * F) + l16 * 2;
        dp[0] = accA;
        dp[1] = accB;
    }
}

// ---------------------------------------------------------------------------
// Launch
// ---------------------------------------------------------------------------
extern "C" void kernel_launch(void* const* d_in, const int* in_sizes, int n_in,
                              void* d_out, int out_size)
{
    const float* x  = (const float*)d_in[0];
    const int*   ei = (const int*)d_in[1];
    const float* W1 = (const float*)d_in[2];
    const float* b1 = (const float*)d_in[3];
    const float* W2 = (const float*)d_in[4];
    const float* b2 = (const float*)d_in[5];
    float*       out = (float*)d_out;

    const int N = in_sizes[0] / F;   // 100000
    const int E = in_sizes[1] / 2;   // 640000

    __half* xwh;   cudaGetSymbolAddress((void**)&xwh,   g_xw_h);
    __half* acc1h; cudaGetSymbolAddress((void**)&acc1h, g_acc1h);
    __half* hwh;   cudaGetSymbolAddress((void**)&hwh,   g_hw_h);
    int* cursor;   cudaGetSymbolAddress((void**)&cursor, g_cursor);

    cudaFuncSetAttribute(k_mega1, cudaFuncAttributeMaxDynamicSharedMemorySize, SMEM_BYTES_G1);
    cudaFuncSetAttribute(k_gemm2, cudaFuncAttributeMaxDynamicSharedMemorySize, SMEM_BYTES_G2);

    const int gemm_blocks = (N + BM - 1) / BM;
    const int scat_blocks = (E + 255) / 256;
    const int nwarp       = (N + 1) / 2;          // two nodes per warp
    const int agg_blocks  = (nwarp + 7) / 8;      // 8 warps per block

    // Zero bucket cursors + overflow counter
    cudaMemsetAsync(cursor, 0, (NMAX + 1) * sizeof(int));

    // W pre-split (both layers, one launch)
    k_wsplit<<<128, 256>>>(W1, W2);

    // GEMM1 + edge scatter fused: xw_h = (x @ W1) as fp16
    k_mega1<<<gemm_blocks + scat_blocks, 256, SMEM_BYTES_G1>>>(x, xwh, ei, N, E, gemm_blocks);

    // dinv table (needs final cursor counts)
    k_dinv<<<(N + 255) / 256, 256>>>(N);

    // Layer 1 aggregation: acc1h = relu(Â·xw_h + b1) as fp16
    k_agg<true><<<agg_blocks, 256>>>(xwh, b1, acc1h, N);

    // Layer 2 GEMM: hw_h = (acc1h @ W2) as fp16  (cp.async fill, 2-term fp16)
    k_gemm2<<<gemm_blocks, 256, SMEM_BYTES_G2>>>(acc1h, hwh, N);

    // Final aggregation: out = Â·hw_h + b2  (fp32)
    k_agg<false><<<agg_blocks, 256>>>(hwh, b2, out, N);
}